// round 1
// baseline (speedup 1.0000x reference)
#include <cuda_runtime.h>

// Problem constants (fixed by setup_inputs)
#define BB 4
#define CC 128
#define HH 64
#define WW 64
#define OO 128
#define TT 9

// Scratch for sampling metadata produced by k1, consumed by k2.
// Per (b,h) row-block: 9 taps x 64 pixels.
__device__ float4 g_wt[BB * HH * TT * WW];  // bilinear weights * mask (zeroed if corner invalid)
__device__ int2   g_xy[BB * HH * TT * WW];  // raw floor coords (y0, x0)

// ---- packed f32x2 helpers (Blackwell FFMA2 path) ----
__device__ __forceinline__ unsigned long long pack2(float a, float b) {
    unsigned long long r;
    asm("mov.b64 %0, {%1, %2};"
        : "=l"(r) : "r"(__float_as_uint(a)), "r"(__float_as_uint(b)));
    return r;
}
__device__ __forceinline__ void unpack2(unsigned long long v, float& a, float& b) {
    unsigned int lo, hi;
    asm("mov.b64 {%0, %1}, %2;" : "=r"(lo), "=r"(hi) : "l"(v));
    a = __uint_as_float(lo);
    b = __uint_as_float(hi);
}
__device__ __forceinline__ void fma2(unsigned long long& d,
                                     unsigned long long a,
                                     unsigned long long b) {
    asm("fma.rn.f32x2 %0, %1, %2, %0;" : "+l"(d) : "l"(a), "l"(b));
}

// ============================================================================
// Kernel 1: 27-channel conv (18 offset + 9 mask channels) + sampling metadata.
// grid = B*H (256) blocks, one (b, h) row each. block = 256 = 64 w-lanes x 4
// channel-groups of 32 input channels. Weights staged in smem as [c*9+k][28]
// so each thread reads 14 x LDS.64 (uniform/broadcast) per x value and does
// 14 FFMA2 into a packed 28-channel accumulator.
// ============================================================================
__global__ __launch_bounds__(256) void k1_sample_meta(
    const float* __restrict__ x,
    const float* __restrict__ ow, const float* __restrict__ ob,
    const float* __restrict__ mw, const float* __restrict__ mb)
{
    extern __shared__ float sm1[];
    float* wsm = sm1;              // [1152][28]  (27 used, 1 pad)
    float* red = sm1 + 1152 * 28;  // [4 cg][28 oc][64 w]

    const int bh = blockIdx.x;
    const int b = bh >> 6, h = bh & 63;
    const int tid = threadIdx.x;
    const int w = tid & 63, cg = tid >> 6;

    // Stage conv weights: dest layout [r=c*9+k][oc], oc 0..17 offset, 18..26 mask
    for (int i = tid; i < 27 * 1152; i += 256) {
        int oc = i / 1152;
        int r = i - oc * 1152;
        float v = (oc < 18) ? ow[oc * 1152 + r] : mw[(oc - 18) * 1152 + r];
        wsm[r * 28 + oc] = v;
    }
    // init pad lane so FFMA2 never sees garbage
    for (int i = tid; i < 1152; i += 256) wsm[i * 28 + 27] = 0.f;
    __syncthreads();

    unsigned long long acc2[14];
#pragma unroll
    for (int q = 0; q < 14; q++) acc2[q] = 0ull;

    const float* xb = x + b * CC * HH * WW;
    for (int c = cg * 32; c < cg * 32 + 32; c++) {
        const float* xp = xb + c * HH * WW;
#pragma unroll
        for (int kh = 0; kh < 3; kh++) {
            int yy = h + kh - 1;
            if ((unsigned)yy >= (unsigned)HH) continue;
#pragma unroll
            for (int kw = 0; kw < 3; kw++) {
                int xx = w + kw - 1;
                if ((unsigned)xx >= (unsigned)WW) continue;
                float xv = xp[yy * WW + xx];
                unsigned long long xv2 = pack2(xv, xv);
                const unsigned long long* wp =
                    (const unsigned long long*)&wsm[(c * 9 + kh * 3 + kw) * 28];
#pragma unroll
                for (int q = 0; q < 14; q++) fma2(acc2[q], xv2, wp[q]);
            }
        }
    }

    // partial sums -> smem
#pragma unroll
    for (int q = 0; q < 14; q++) {
        float a, b2;
        unpack2(acc2[q], a, b2);
        red[(cg * 28 + 2 * q) * 64 + w] = a;
        red[(cg * 28 + 2 * q + 1) * 64 + w] = b2;
    }
    __syncthreads();

    // Reduce 4 groups, add bias, sigmoid mask, compute bilinear metadata.
    // 9 taps x 64 pixels = 576 items.
    for (int i = tid; i < TT * 64; i += 256) {
        int t = i >> 6, ww = i & 63;
        float s0 = 0.f, s1 = 0.f, s2 = 0.f;
#pragma unroll
        for (int g = 0; g < 4; g++) {
            s0 += red[(g * 28 + 2 * t) * 64 + ww];
            s1 += red[(g * 28 + 2 * t + 1) * 64 + ww];
            s2 += red[(g * 28 + 18 + t) * 64 + ww];
        }
        float offy = s0 + ob[2 * t];
        float offx = s1 + ob[2 * t + 1];
        float m = 1.f / (1.f + __expf(-(s2 + mb[t])));

        int ii = t / 3;
        int jj = t - ii * 3;
        float py = (float)(h - 1 + ii) + offy;
        float px = (float)(ww - 1 + jj) + offx;
        float fy = floorf(py), fx = floorf(px);
        float ly = py - fy, lx = px - fx;
        int y0 = (int)fy, x0 = (int)fx;
        float hy = 1.f - ly, hx = 1.f - lx;
        float w00 = hy * hx * m, w01 = hy * lx * m;
        float w10 = ly * hx * m, w11 = ly * lx * m;
        bool vy0 = (unsigned)y0 < 64u;
        bool vy1 = (unsigned)(y0 + 1) < 64u;
        bool vx0 = (unsigned)x0 < 64u;
        bool vx1 = (unsigned)(x0 + 1) < 64u;
        if (!(vy0 && vx0)) w00 = 0.f;
        if (!(vy0 && vx1)) w01 = 0.f;
        if (!(vy1 && vx0)) w10 = 0.f;
        if (!(vy1 && vx1)) w11 = 0.f;
        g_wt[bh * 576 + i] = make_float4(w00, w01, w10, w11);
        g_xy[bh * 576 + i] = make_int2(y0, x0);
    }
}

// ============================================================================
// Kernel 2: deformable sampling + implicit GEMM + BN + SiLU.
// grid = B*H (256), one (b, h) row of 64 pixels x all 128 output channels.
// block = 256: thread tile = 4 o (o0 = (tid&31)*4) x 8 px (px0 = (tid>>5)*8).
// Loop over 16 chunks of 8 input channels:
//   - stage weight chunk wsm[r=c'*9+t][128 o] (pad stride 132)
//   - stage sampled vals val[r][64 px] (bilinear, 4 clamped gathers)
//   - accumulate 72 x (1 LDS.128 wgt + 2 LDS.128 val + 4 packs + 16 FFMA2)
// ============================================================================
__global__ __launch_bounds__(256) void k2_deform_gemm(
    const float* __restrict__ x, const float* __restrict__ wgt,
    const float* __restrict__ gamma, const float* __restrict__ beta,
    const float* __restrict__ mean, const float* __restrict__ var,
    float* __restrict__ out)
{
    extern __shared__ float sm2[];
    float* wsm = sm2;               // [72][132]
    float* val = sm2 + 72 * 132;    // [72][64]
    float4* mwt = (float4*)(val + 72 * 64);  // [9][64]
    int2* mxy = (int2*)(mwt + 576);          // [9][64]

    const int bh = blockIdx.x;
    const int b = bh >> 6, h = bh & 63;
    const int tid = threadIdx.x;

    for (int i = tid; i < 576; i += 256) {
        mwt[i] = g_wt[bh * 576 + i];
        mxy[i] = g_xy[bh * 576 + i];
    }

    const int o0 = (tid & 31) * 4;
    const int px0 = (tid >> 5) * 8;

    float scale[4], shift[4];
#pragma unroll
    for (int j = 0; j < 4; j++) {
        float sc = gamma[o0 + j] * rsqrtf(var[o0 + j] + 1e-5f);
        scale[j] = sc;
        shift[j] = beta[o0 + j] - mean[o0 + j] * sc;
    }

    unsigned long long acc2[4][4];
#pragma unroll
    for (int j = 0; j < 4; j++)
#pragma unroll
        for (int p = 0; p < 4; p++) acc2[j][p] = 0ull;

    const float* xb = x + b * CC * HH * WW;
    __syncthreads();  // metadata ready

    for (int c0 = 0; c0 < CC; c0 += 8) {
        // stage weight chunk: src contiguous 72 floats per o (coalesced)
        for (int i = tid; i < 128 * 72; i += 256) {
            int o = i / 72;
            int r = i - o * 72;
            wsm[r * 132 + o] = wgt[o * 1152 + c0 * 9 + r];
        }
        // stage sampled values: 8 c' x 9 t x 64 px
        for (int i = tid; i < 8 * 9 * 64; i += 256) {
            int px = i & 63;
            int ct = i >> 6;            // c'*9 + t
            int cpr = ct / 9;
            int t = ct - cpr * 9;
            float4 wv = mwt[t * 64 + px];
            int2 xy = mxy[t * 64 + px];
            int y0 = xy.x, x0 = xy.y;
            int y0a = min(max(y0, 0), 63);
            int y1a = min(max(y0 + 1, 0), 63);
            int x0a = min(max(x0, 0), 63);
            int x1a = min(max(x0 + 1, 0), 63);
            const float* xp = xb + (c0 + cpr) * HH * WW;
            float v = wv.x * xp[y0a * 64 + x0a] + wv.y * xp[y0a * 64 + x1a]
                    + wv.z * xp[y1a * 64 + x0a] + wv.w * xp[y1a * 64 + x1a];
            val[ct * 64 + px] = v;
        }
        __syncthreads();

#pragma unroll 9
        for (int r = 0; r < 72; r++) {
            float4 wv = *(const float4*)&wsm[r * 132 + o0];
            unsigned long long w2[4];
            w2[0] = pack2(wv.x, wv.x);
            w2[1] = pack2(wv.y, wv.y);
            w2[2] = pack2(wv.z, wv.z);
            w2[3] = pack2(wv.w, wv.w);
            const ulonglong2* vp = (const ulonglong2*)&val[r * 64 + px0];
            ulonglong2 va = vp[0];
            ulonglong2 vb = vp[1];
            unsigned long long v2[4] = {va.x, va.y, vb.x, vb.y};
#pragma unroll
            for (int j = 0; j < 4; j++)
#pragma unroll
                for (int p = 0; p < 4; p++) fma2(acc2[j][p], w2[j], v2[p]);
        }
        __syncthreads();
    }

    // epilogue: BN affine + SiLU, vectorized stores
#pragma unroll
    for (int j = 0; j < 4; j++) {
        float o8[8];
#pragma unroll
        for (int p = 0; p < 4; p++) {
            float lo, hi;
            unpack2(acc2[j][p], lo, hi);
            o8[2 * p] = lo;
            o8[2 * p + 1] = hi;
        }
        float sc = scale[j], sh = shift[j];
#pragma unroll
        for (int p = 0; p < 8; p++) {
            float v = o8[p] * sc + sh;
            o8[p] = v / (1.f + __expf(-v));
        }
        float* op = out + ((b * OO + o0 + j) * HH + h) * WW + px0;
        *(float4*)op = make_float4(o8[0], o8[1], o8[2], o8[3]);
        *(float4*)(op + 4) = make_float4(o8[4], o8[5], o8[6], o8[7]);
    }
}

extern "C" void kernel_launch(void* const* d_in, const int* in_sizes, int n_in,
                              void* d_out, int out_size)
{
    const float* x  = (const float*)d_in[0];
    const float* ow = (const float*)d_in[1];
    const float* ob = (const float*)d_in[2];
    const float* mw = (const float*)d_in[3];
    const float* mb = (const float*)d_in[4];
    const float* wg = (const float*)d_in[5];
    const float* gg = (const float*)d_in[6];
    const float* bt = (const float*)d_in[7];
    const float* mu = (const float*)d_in[8];
    const float* vr = (const float*)d_in[9];
    float* out = (float*)d_out;

    const int SM1 = (1152 * 28 + 4 * 28 * 64) * 4;                  // 157,696 B
    const int SM2 = (72 * 132 + 72 * 64) * 4 + 576 * 16 + 576 * 8;  // 70,272 B
    cudaFuncSetAttribute(k1_sample_meta,
                         cudaFuncAttributeMaxDynamicSharedMemorySize, SM1);
    cudaFuncSetAttribute(k2_deform_gemm,
                         cudaFuncAttributeMaxDynamicSharedMemorySize, SM2);

    k1_sample_meta<<<BB * HH, 256, SM1>>>(x, ow, ob, mw, mb);
    k2_deform_gemm<<<BB * HH, 256, SM2>>>(x, wg, gg, bt, mu, vr, out);
}

// round 3
// speedup vs baseline: 1.3013x; 1.3013x over previous
#include <cuda_runtime.h>
#include <cuda_bf16.h>
#include <cstdint>

// Problem constants (fixed by setup_inputs)
#define BB 4
#define CC 128
#define HH 64
#define WW 64
#define OO 128
#define TT 9

// Sampling metadata: per (b,h) row: 9 taps x 64 pixels.
__device__ float4  g_wt[BB * HH * TT * WW];   // bilinear weights * mask (0 if invalid)
__device__ ushort4 g_offp[BB * HH * TT * WW]; // clamped flat offsets (y*64+x), 4 corners

// ---------------------------------------------------------------------------
// helpers
// ---------------------------------------------------------------------------
__device__ __forceinline__ unsigned long long pack2(float a, float b) {
    unsigned long long r;
    asm("mov.b64 %0, {%1, %2};"
        : "=l"(r) : "r"(__float_as_uint(a)), "r"(__float_as_uint(b)));
    return r;
}
__device__ __forceinline__ void unpack2(unsigned long long v, float& a, float& b) {
    unsigned int lo, hi;
    asm("mov.b64 {%0, %1}, %2;" : "=r"(lo), "=r"(hi) : "l"(v));
    a = __uint_as_float(lo);
    b = __uint_as_float(hi);
}
__device__ __forceinline__ void fma2(unsigned long long& d,
                                     unsigned long long a,
                                     unsigned long long b) {
    asm("fma.rn.f32x2 %0, %1, %2, %0;" : "+l"(d) : "l"(a), "l"(b));
}
__device__ __forceinline__ uint32_t smem_u32(const void* p) {
    uint32_t a;
    asm("{ .reg .u64 t; cvta.to.shared.u64 t, %1; cvt.u32.u64 %0, t; }"
        : "=r"(a) : "l"(p));
    return a;
}
#define SWZ128(o) ((o) ^ (((o) >> 3) & 0x70))

__device__ __forceinline__ void ldsm_x4(uint32_t* r, uint32_t addr) {
    asm volatile("ldmatrix.sync.aligned.m8n8.x4.shared.b16 {%0,%1,%2,%3}, [%4];"
                 : "=r"(r[0]), "=r"(r[1]), "=r"(r[2]), "=r"(r[3]) : "r"(addr));
}
__device__ __forceinline__ void mma_bf16(float* c, const uint32_t* a,
                                         const uint32_t* b) {
    asm volatile("mma.sync.aligned.m16n8k16.row.col.f32.bf16.bf16.f32 "
                 "{%0,%1,%2,%3}, {%4,%5,%6,%7}, {%8,%9}, {%0,%1,%2,%3};"
                 : "+f"(c[0]), "+f"(c[1]), "+f"(c[2]), "+f"(c[3])
                 : "r"(a[0]), "r"(a[1]), "r"(a[2]), "r"(a[3]),
                   "r"(b[0]), "r"(b[1]));
}
__device__ __forceinline__ uint32_t bf16split_hi(float v0, float v1, uint32_t& lw) {
    __nv_bfloat16 h0 = __float2bfloat16(v0);
    __nv_bfloat16 h1 = __float2bfloat16(v1);
    __nv_bfloat16 l0 = __float2bfloat16(v0 - __bfloat162float(h0));
    __nv_bfloat16 l1 = __float2bfloat16(v1 - __bfloat162float(h1));
    lw = ((uint32_t)__bfloat16_as_ushort(l1) << 16) | __bfloat16_as_ushort(l0);
    return ((uint32_t)__bfloat16_as_ushort(h1) << 16) | __bfloat16_as_ushort(h0);
}

// ============================================================================
// Kernel 1: 27-channel conv (18 offset + 9 mask) + bilinear sampling metadata.
// (math identical to the R1 passing kernel; offsets packed to ushort4)
// ============================================================================
__global__ __launch_bounds__(256) void k1_sample_meta(
    const float* __restrict__ x,
    const float* __restrict__ ow, const float* __restrict__ ob,
    const float* __restrict__ mw, const float* __restrict__ mb)
{
    extern __shared__ float sm1[];
    float* wsm = sm1;              // [1152][28]
    float* red = sm1 + 1152 * 28;  // [4][28][64]

    const int bh = blockIdx.x;
    const int b = bh >> 6, h = bh & 63;
    const int tid = threadIdx.x;
    const int w = tid & 63, cg = tid >> 6;

    for (int i = tid; i < 27 * 1152; i += 256) {
        int oc = i / 1152;
        int r = i - oc * 1152;
        float v = (oc < 18) ? ow[oc * 1152 + r] : mw[(oc - 18) * 1152 + r];
        wsm[r * 28 + oc] = v;
    }
    for (int i = tid; i < 1152; i += 256) wsm[i * 28 + 27] = 0.f;
    __syncthreads();

    unsigned long long acc2[14];
#pragma unroll
    for (int q = 0; q < 14; q++) acc2[q] = 0ull;

    const float* xb = x + b * CC * HH * WW;
    for (int c = cg * 32; c < cg * 32 + 32; c++) {
        const float* xp = xb + c * HH * WW;
#pragma unroll
        for (int kh = 0; kh < 3; kh++) {
            int yy = h + kh - 1;
            if ((unsigned)yy >= (unsigned)HH) continue;
#pragma unroll
            for (int kw = 0; kw < 3; kw++) {
                int xx = w + kw - 1;
                if ((unsigned)xx >= (unsigned)WW) continue;
                float xv = xp[yy * WW + xx];
                unsigned long long xv2 = pack2(xv, xv);
                const unsigned long long* wp =
                    (const unsigned long long*)&wsm[(c * 9 + kh * 3 + kw) * 28];
#pragma unroll
                for (int q = 0; q < 14; q++) fma2(acc2[q], xv2, wp[q]);
            }
        }
    }

#pragma unroll
    for (int q = 0; q < 14; q++) {
        float a, b2;
        unpack2(acc2[q], a, b2);
        red[(cg * 28 + 2 * q) * 64 + w] = a;
        red[(cg * 28 + 2 * q + 1) * 64 + w] = b2;
    }
    __syncthreads();

    for (int i = tid; i < TT * 64; i += 256) {
        int t = i >> 6, ww = i & 63;
        float s0 = 0.f, s1 = 0.f, s2 = 0.f;
#pragma unroll
        for (int g = 0; g < 4; g++) {
            s0 += red[(g * 28 + 2 * t) * 64 + ww];
            s1 += red[(g * 28 + 2 * t + 1) * 64 + ww];
            s2 += red[(g * 28 + 18 + t) * 64 + ww];
        }
        float offy = s0 + ob[2 * t];
        float offx = s1 + ob[2 * t + 1];
        float m = 1.f / (1.f + __expf(-(s2 + mb[t])));

        int ii = t / 3;
        int jj = t - ii * 3;
        float py = (float)(h - 1 + ii) + offy;
        float px = (float)(ww - 1 + jj) + offx;
        float fy = floorf(py), fx = floorf(px);
        float ly = py - fy, lx = px - fx;
        int y0 = (int)fy, x0 = (int)fx;
        float hy = 1.f - ly, hx = 1.f - lx;
        float w00 = hy * hx * m, w01 = hy * lx * m;
        float w10 = ly * hx * m, w11 = ly * lx * m;
        bool vy0 = (unsigned)y0 < 64u;
        bool vy1 = (unsigned)(y0 + 1) < 64u;
        bool vx0 = (unsigned)x0 < 64u;
        bool vx1 = (unsigned)(x0 + 1) < 64u;
        if (!(vy0 && vx0)) w00 = 0.f;
        if (!(vy0 && vx1)) w01 = 0.f;
        if (!(vy1 && vx0)) w10 = 0.f;
        if (!(vy1 && vx1)) w11 = 0.f;
        int y0a = min(max(y0, 0), 63), y1a = min(max(y0 + 1, 0), 63);
        int x0a = min(max(x0, 0), 63), x1a = min(max(x0 + 1, 0), 63);
        g_wt[bh * 576 + i] = make_float4(w00, w01, w10, w11);
        g_offp[bh * 576 + i] =
            make_ushort4((unsigned short)(y0a * 64 + x0a),
                         (unsigned short)(y0a * 64 + x1a),
                         (unsigned short)(y1a * 64 + x0a),
                         (unsigned short)(y1a * 64 + x1a));
    }
}

// ============================================================================
// Kernel 2: deformable sampling (bf16 hi/lo) + mma.sync bf16 GEMM + BN + SiLU.
// grid = 128 (M-tile = 128 px), block = 256 (8 warps, 2Mx4N, warp 64x32).
// K = 1152 in 18 chunks of 64, double-buffered SW128 smem, 3-pass split-bf16.
// ============================================================================
#define SM_WT  131072   // float4[1152]
#define SM_OFF 149504   // ushort4[1152]
#define SM_SC  158720   // float[128]
#define SM_SH  159232   // float[128]
#define SM2_BYTES 159744

__device__ __forceinline__ void stage_chunk(
    char* bufA_hi, const float* __restrict__ xb, const float* __restrict__ wgt,
    const float4* __restrict__ s_wt, const ushort4* __restrict__ s_off,
    int k0, int tid)
{
    char* bufA_lo = bufA_hi + 16384;
    char* bufB_hi = bufA_hi + 32768;
    char* bufB_lo = bufA_hi + 49152;

    // A: 128 m x 32 kp; warp covers 8 m x 4 kp (conflict-free STS, coalesced LDG)
#pragma unroll 2
    for (int it = 0; it < 16; it++) {
        int id = it * 256 + tid;
        int m = (id & 7) | (((id >> 5) & 15) << 3);
        int kp = ((id >> 3) & 3) | ((id >> 9) << 2);
        int k = k0 + kp * 2;

        unsigned c0 = (unsigned)k / 9u;
        int t0 = k - c0 * 9;
        unsigned c1 = (unsigned)(k + 1) / 9u;
        int t1 = (k + 1) - c1 * 9;
        int mr = ((m >> 6) * 576) + (m & 63);

        float4 w0 = s_wt[mr + t0 * 64];
        ushort4 o0 = s_off[mr + t0 * 64];
        const float* xp0 = xb + c0 * 4096;
        float v0 = w0.x * xp0[o0.x] + w0.y * xp0[o0.y]
                 + w0.z * xp0[o0.z] + w0.w * xp0[o0.w];

        float4 w1 = s_wt[mr + t1 * 64];
        ushort4 o1 = s_off[mr + t1 * 64];
        const float* xp1 = xb + c1 * 4096;
        float v1 = w1.x * xp1[o1.x] + w1.y * xp1[o1.y]
                 + w1.z * xp1[o1.z] + w1.w * xp1[o1.w];

        uint32_t lw, hw = bf16split_hi(v0, v1, lw);
        uint32_t off = SWZ128((uint32_t)(m * 128 + kp * 4));
        *(uint32_t*)(bufA_hi + off) = hw;
        *(uint32_t*)(bufA_lo + off) = lw;
    }

    // B: 128 o x 32 kp; warp = 1 o x 32 kp (conflict-free STS, 256B coalesced LDG)
#pragma unroll 4
    for (int it = 0; it < 16; it++) {
        int id = it * 256 + tid;
        int o = id >> 5, kp = id & 31;
        float2 wv = *(const float2*)(wgt + o * 1152 + k0 + kp * 2);
        uint32_t lw, hw = bf16split_hi(wv.x, wv.y, lw);
        uint32_t off = SWZ128((uint32_t)(o * 128 + kp * 4));
        *(uint32_t*)(bufB_hi + off) = hw;
        *(uint32_t*)(bufB_lo + off) = lw;
    }
}

__global__ __launch_bounds__(256, 1) void k2_deform_mma(
    const float* __restrict__ x, const float* __restrict__ wgt,
    const float* __restrict__ gamma, const float* __restrict__ beta,
    const float* __restrict__ mean, const float* __restrict__ var,
    float* __restrict__ out)
{
    extern __shared__ char sm[];
    const uint32_t sb = smem_u32(sm);
    const int tid = threadIdx.x;
    const int wid = tid >> 5, lid = tid & 31;
    const int blk = blockIdx.x;
    const int b = blk >> 5;
    const int h0 = (blk & 31) * 2;

    float4* s_wt = (float4*)(sm + SM_WT);
    ushort4* s_off = (ushort4*)(sm + SM_OFF);
    float* s_sc = (float*)(sm + SM_SC);
    float* s_sh = (float*)(sm + SM_SH);

    const int mbase = (b * 64 + h0) * 576;
    for (int i = tid; i < 1152; i += 256) {
        s_wt[i] = g_wt[mbase + i];
        s_off[i] = g_offp[mbase + i];
    }
    if (tid < 128) {
        float sc = gamma[tid] * rsqrtf(var[tid] + 1e-5f);
        s_sc[tid] = sc;
        s_sh[tid] = beta[tid] - mean[tid] * sc;
    }
    const float* xb = x + b * CC * HH * WW;
    __syncthreads();

    // warp layout: wM in {0,64}, wN in {0,32,64,96}
    const int wM = (wid & 1) * 64;
    const int wN = (wid >> 1) * 32;
    // ldmatrix per-lane address components
    const int a_row = lid & 15;
    const int a_col = (lid >> 4) * 8;
    const int b_row = (lid & 7) + ((lid >> 4) << 3);
    const int b_col = ((lid >> 3) & 1) * 8;

    float acc[4][4][4];
#pragma unroll
    for (int mt = 0; mt < 4; mt++)
#pragma unroll
        for (int nt = 0; nt < 4; nt++)
#pragma unroll
            for (int i = 0; i < 4; i++) acc[mt][nt][i] = 0.f;

    stage_chunk(sm, xb, wgt, s_wt, s_off, 0, tid);
    __syncthreads();

    for (int ch = 0; ch < 18; ch++) {
        const int cur = ch & 1;
        const uint32_t baseA = sb + cur * 65536;

#pragma unroll
        for (int ks = 0; ks < 4; ks++) {
            uint32_t ah[4][4], al[4][4];
#pragma unroll
            for (int mt = 0; mt < 4; mt++) {
                uint32_t off = SWZ128((uint32_t)((wM + mt * 16 + a_row) * 128 +
                                                 (ks * 16 + a_col) * 2));
                ldsm_x4(ah[mt], baseA + off);
                ldsm_x4(al[mt], baseA + 16384 + off);
            }
            uint32_t bh[2][4], bl[2][4];
#pragma unroll
            for (int p = 0; p < 2; p++) {
                uint32_t off = SWZ128((uint32_t)((wN + p * 16 + b_row) * 128 +
                                                 (ks * 16 + b_col) * 2));
                ldsm_x4(bh[p], baseA + 32768 + off);
                ldsm_x4(bl[p], baseA + 49152 + off);
            }
#pragma unroll
            for (int mt = 0; mt < 4; mt++)
#pragma unroll
                for (int nt = 0; nt < 4; nt++) {
                    const uint32_t* bhp = &bh[nt >> 1][(nt & 1) * 2];
                    const uint32_t* blp = &bl[nt >> 1][(nt & 1) * 2];
                    mma_bf16(acc[mt][nt], ah[mt], bhp);
                    mma_bf16(acc[mt][nt], ah[mt], blp);
                    mma_bf16(acc[mt][nt], al[mt], bhp);
                }
        }

        if (ch < 17)
            stage_chunk(sm + (cur ^ 1) * 65536, xb, wgt, s_wt, s_off,
                        (ch + 1) * 64, tid);
        __syncthreads();
    }

    // epilogue: BN + SiLU + store. frag: c0:(g,2t) c1:(g,2t+1) c2:(g+8,2t) c3:(g+8,2t+1)
    const int g = lid >> 2, t2 = (lid & 3) * 2;
#pragma unroll
    for (int mt = 0; mt < 4; mt++) {
#pragma unroll
        for (int nt = 0; nt < 4; nt++) {
#pragma unroll
            for (int i = 0; i < 4; i++) {
                int m = wM + mt * 16 + g + ((i >> 1) ? 8 : 0);
                int n = wN + nt * 8 + t2 + (i & 1);
                float v = acc[mt][nt][i] * s_sc[n] + s_sh[n];
                v = v / (1.f + __expf(-v));
                int h = h0 + (m >> 6), w = m & 63;
                out[((b * OO + n) * HH + h) * WW + w] = v;
            }
        }
    }
}

extern "C" void kernel_launch(void* const* d_in, const int* in_sizes, int n_in,
                              void* d_out, int out_size)
{
    const float* x  = (const float*)d_in[0];
    const float* ow = (const float*)d_in[1];
    const float* ob = (const float*)d_in[2];
    const float* mw = (const float*)d_in[3];
    const float* mb = (const float*)d_in[4];
    const float* wg = (const float*)d_in[5];
    const float* gg = (const float*)d_in[6];
    const float* bt = (const float*)d_in[7];
    const float* mu = (const float*)d_in[8];
    const float* vr = (const float*)d_in[9];
    float* out = (float*)d_out;

    const int SM1 = (1152 * 28 + 4 * 28 * 64) * 4;  // 157,696 B
    cudaFuncSetAttribute(k1_sample_meta,
                         cudaFuncAttributeMaxDynamicSharedMemorySize, SM1);
    cudaFuncSetAttribute(k2_deform_mma,
                         cudaFuncAttributeMaxDynamicSharedMemorySize, SM2_BYTES);

    k1_sample_meta<<<BB * HH, 256, SM1>>>(x, ow, ob, mw, mb);
    k2_deform_mma<<<128, 256, SM2_BYTES>>>(x, wg, gg, bt, mu, vr, out);
}

// round 4
// speedup vs baseline: 1.6115x; 1.2383x over previous
#include <cuda_runtime.h>
#include <cuda_bf16.h>
#include <cstdint>

// Problem constants (fixed by setup_inputs)
#define BB 4
#define CC 128
#define HH 64
#define WW 64
#define OO 128
#define TT 9

// Sampling metadata: per (b,h) row: 9 taps x 64 pixels.
__device__ float4  g_wt[BB * HH * TT * WW];   // bilinear weights * mask (0 if invalid)
__device__ ushort4 g_offp[BB * HH * TT * WW]; // clamped flat offsets (y*64+x), 4 corners
// Pre-split, pre-swizzled bf16 weights: [18 chunks][hi 16KB | lo 16KB]
__device__ char g_wb[18 * 32768];

// ---------------------------------------------------------------------------
// helpers
// ---------------------------------------------------------------------------
__device__ __forceinline__ unsigned long long pack2(float a, float b) {
    unsigned long long r;
    asm("mov.b64 %0, {%1, %2};"
        : "=l"(r) : "r"(__float_as_uint(a)), "r"(__float_as_uint(b)));
    return r;
}
__device__ __forceinline__ void unpack2(unsigned long long v, float& a, float& b) {
    unsigned int lo, hi;
    asm("mov.b64 {%0, %1}, %2;" : "=r"(lo), "=r"(hi) : "l"(v));
    a = __uint_as_float(lo);
    b = __uint_as_float(hi);
}
__device__ __forceinline__ void fma2(unsigned long long& d,
                                     unsigned long long a,
                                     unsigned long long b) {
    asm("fma.rn.f32x2 %0, %1, %2, %0;" : "+l"(d) : "l"(a), "l"(b));
}
__device__ __forceinline__ uint32_t smem_u32(const void* p) {
    uint32_t a;
    asm("{ .reg .u64 t; cvta.to.shared.u64 t, %1; cvt.u32.u64 %0, t; }"
        : "=r"(a) : "l"(p));
    return a;
}
#define SWZ128(o) ((o) ^ (((o) >> 3) & 0x70))

__device__ __forceinline__ void ldsm_x4(uint32_t* r, uint32_t addr) {
    asm volatile("ldmatrix.sync.aligned.m8n8.x4.shared.b16 {%0,%1,%2,%3}, [%4];"
                 : "=r"(r[0]), "=r"(r[1]), "=r"(r[2]), "=r"(r[3]) : "r"(addr));
}
__device__ __forceinline__ void mma_bf16(float* c, const uint32_t* a,
                                         const uint32_t* b) {
    asm volatile("mma.sync.aligned.m16n8k16.row.col.f32.bf16.bf16.f32 "
                 "{%0,%1,%2,%3}, {%4,%5,%6,%7}, {%8,%9}, {%0,%1,%2,%3};"
                 : "+f"(c[0]), "+f"(c[1]), "+f"(c[2]), "+f"(c[3])
                 : "r"(a[0]), "r"(a[1]), "r"(a[2]), "r"(a[3]),
                   "r"(b[0]), "r"(b[1]));
}
__device__ __forceinline__ uint32_t bf16split_hi(float v0, float v1, uint32_t& lw) {
    __nv_bfloat16 h0 = __float2bfloat16(v0);
    __nv_bfloat16 h1 = __float2bfloat16(v1);
    __nv_bfloat16 l0 = __float2bfloat16(v0 - __bfloat162float(h0));
    __nv_bfloat16 l1 = __float2bfloat16(v1 - __bfloat162float(h1));
    lw = ((uint32_t)__bfloat16_as_ushort(l1) << 16) | __bfloat16_as_ushort(l0);
    return ((uint32_t)__bfloat16_as_ushort(h1) << 16) | __bfloat16_as_ushort(h0);
}
__device__ __forceinline__ void cp_async16(uint32_t smem_dst, const void* gsrc) {
    asm volatile("cp.async.cg.shared.global [%0], [%1], 16;"
                 :: "r"(smem_dst), "l"(gsrc) : "memory");
}
__device__ __forceinline__ void cp_commit() {
    asm volatile("cp.async.commit_group;" ::: "memory");
}
__device__ __forceinline__ void cp_wait0() {
    asm volatile("cp.async.wait_group 0;" ::: "memory");
}

// ============================================================================
// Kernel 0: split weights into bf16 hi/lo, pre-swizzled per-chunk tiles.
// ============================================================================
__global__ __launch_bounds__(256) void k0_split_weights(const float* __restrict__ wgt)
{
    int id = blockIdx.x * 256 + threadIdx.x;  // 73728 items
    int ch = id >> 12;
    int r = id & 4095;
    int o = r >> 5, kp = r & 31;
    float2 wv = *(const float2*)(wgt + o * 1152 + ch * 64 + kp * 2);
    uint32_t lw, hw = bf16split_hi(wv.x, wv.y, lw);
    uint32_t off = SWZ128((uint32_t)(o * 128 + kp * 4));
    *(uint32_t*)(g_wb + ch * 32768 + off) = hw;
    *(uint32_t*)(g_wb + ch * 32768 + 16384 + off) = lw;
}

// ============================================================================
// Kernel 1: 27-channel conv (18 offset + 9 mask) + bilinear sampling metadata.
// ============================================================================
__global__ __launch_bounds__(256) void k1_sample_meta(
    const float* __restrict__ x,
    const float* __restrict__ ow, const float* __restrict__ ob,
    const float* __restrict__ mw, const float* __restrict__ mb)
{
    extern __shared__ float sm1[];
    float* wsm = sm1;              // [1152][28]
    float* red = sm1 + 1152 * 28;  // [4][28][64]

    const int bh = blockIdx.x;
    const int b = bh >> 6, h = bh & 63;
    const int tid = threadIdx.x;
    const int w = tid & 63, cg = tid >> 6;

    for (int i = tid; i < 27 * 1152; i += 256) {
        int oc = i / 1152;
        int r = i - oc * 1152;
        float v = (oc < 18) ? ow[oc * 1152 + r] : mw[(oc - 18) * 1152 + r];
        wsm[r * 28 + oc] = v;
    }
    for (int i = tid; i < 1152; i += 256) wsm[i * 28 + 27] = 0.f;
    __syncthreads();

    unsigned long long acc2[14];
#pragma unroll
    for (int q = 0; q < 14; q++) acc2[q] = 0ull;

    const float* xb = x + b * CC * HH * WW;
    for (int c = cg * 32; c < cg * 32 + 32; c++) {
        const float* xp = xb + c * HH * WW;
#pragma unroll
        for (int kh = 0; kh < 3; kh++) {
            int yy = h + kh - 1;
            if ((unsigned)yy >= (unsigned)HH) continue;
#pragma unroll
            for (int kw = 0; kw < 3; kw++) {
                int xx = w + kw - 1;
                if ((unsigned)xx >= (unsigned)WW) continue;
                float xv = xp[yy * WW + xx];
                unsigned long long xv2 = pack2(xv, xv);
                const ulonglong2* wp =
                    (const ulonglong2*)&wsm[(c * 9 + kh * 3 + kw) * 28];
#pragma unroll
                for (int q = 0; q < 7; q++) {
                    ulonglong2 u = wp[q];
                    fma2(acc2[2 * q], xv2, u.x);
                    fma2(acc2[2 * q + 1], xv2, u.y);
                }
            }
        }
    }

#pragma unroll
    for (int q = 0; q < 14; q++) {
        float a, b2;
        unpack2(acc2[q], a, b2);
        red[(cg * 28 + 2 * q) * 64 + w] = a;
        red[(cg * 28 + 2 * q + 1) * 64 + w] = b2;
    }
    __syncthreads();

    for (int i = tid; i < TT * 64; i += 256) {
        int t = i >> 6, ww = i & 63;
        float s0 = 0.f, s1 = 0.f, s2 = 0.f;
#pragma unroll
        for (int g = 0; g < 4; g++) {
            s0 += red[(g * 28 + 2 * t) * 64 + ww];
            s1 += red[(g * 28 + 2 * t + 1) * 64 + ww];
            s2 += red[(g * 28 + 18 + t) * 64 + ww];
        }
        float offy = s0 + ob[2 * t];
        float offx = s1 + ob[2 * t + 1];
        float m = 1.f / (1.f + __expf(-(s2 + mb[t])));

        int ii = t / 3;
        int jj = t - ii * 3;
        float py = (float)(h - 1 + ii) + offy;
        float px = (float)(ww - 1 + jj) + offx;
        float fy = floorf(py), fx = floorf(px);
        float ly = py - fy, lx = px - fx;
        int y0 = (int)fy, x0 = (int)fx;
        float hy = 1.f - ly, hx = 1.f - lx;
        float w00 = hy * hx * m, w01 = hy * lx * m;
        float w10 = ly * hx * m, w11 = ly * lx * m;
        bool vy0 = (unsigned)y0 < 64u;
        bool vy1 = (unsigned)(y0 + 1) < 64u;
        bool vx0 = (unsigned)x0 < 64u;
        bool vx1 = (unsigned)(x0 + 1) < 64u;
        if (!(vy0 && vx0)) w00 = 0.f;
        if (!(vy0 && vx1)) w01 = 0.f;
        if (!(vy1 && vx0)) w10 = 0.f;
        if (!(vy1 && vx1)) w11 = 0.f;
        int y0a = min(max(y0, 0), 63), y1a = min(max(y0 + 1, 0), 63);
        int x0a = min(max(x0, 0), 63), x1a = min(max(x0 + 1, 0), 63);
        g_wt[bh * 576 + i] = make_float4(w00, w01, w10, w11);
        g_offp[bh * 576 + i] =
            make_ushort4((unsigned short)(y0a * 64 + x0a),
                         (unsigned short)(y0a * 64 + x1a),
                         (unsigned short)(y1a * 64 + x0a),
                         (unsigned short)(y1a * 64 + x1a));
    }
}

// ============================================================================
// Kernel 2: deformable sampling (bf16 hi/lo) + mma.sync bf16 GEMM + BN + SiLU.
// grid = 256 (one image row, M=64), block = 256 (8 warps, 2Mx4N, warp 32x32).
// K = 1152 in 18 chunks of 64; A gathered+split in-kernel, B via cp.async from
// pre-split g_wb; double-buffered; 2 CTAs/SM.
// Buffer layout per stage (48KB): A_hi 8K | A_lo 8K | B_hi 16K | B_lo 16K.
// ============================================================================
#define SM_WT  98304    // float4[576]
#define SM_OFF 107520   // ushort4[576]
#define SM_SC  112128   // float[128]
#define SM_SH  112640   // float[128]
#define SM2_BYTES 113152

__device__ __forceinline__ void stage_A(
    char* buf, const float* __restrict__ xb,
    const float4* __restrict__ s_wt, const ushort4* __restrict__ s_off,
    int k0, int tid)
{
    char* alo = buf + 8192;
#pragma unroll
    for (int it = 0; it < 8; it++) {
        int id = it * 256 + tid;
        int m = (id & 7) | (((id >> 5) & 7) << 3);
        int kp = ((id >> 3) & 3) | ((id >> 8) << 2);
        int k = k0 + kp * 2;

        unsigned c0 = (unsigned)k / 9u;
        int t0 = k - c0 * 9;
        unsigned c1 = (unsigned)(k + 1) / 9u;
        int t1 = (k + 1) - c1 * 9;

        float4 w0 = s_wt[t0 * 64 + m];
        ushort4 o0 = s_off[t0 * 64 + m];
        const float* xp0 = xb + c0 * 4096;
        float v0 = w0.x * xp0[o0.x] + w0.y * xp0[o0.y]
                 + w0.z * xp0[o0.z] + w0.w * xp0[o0.w];

        float4 w1 = s_wt[t1 * 64 + m];
        ushort4 o1 = s_off[t1 * 64 + m];
        const float* xp1 = xb + c1 * 4096;
        float v1 = w1.x * xp1[o1.x] + w1.y * xp1[o1.y]
                 + w1.z * xp1[o1.z] + w1.w * xp1[o1.w];

        uint32_t lw, hw = bf16split_hi(v0, v1, lw);
        uint32_t off = SWZ128((uint32_t)(m * 128 + kp * 4));
        *(uint32_t*)(buf + off) = hw;
        *(uint32_t*)(alo + off) = lw;
    }
}

__global__ __launch_bounds__(256, 2) void k2_deform_mma(
    const float* __restrict__ x,
    const float* __restrict__ gamma, const float* __restrict__ beta,
    const float* __restrict__ mean, const float* __restrict__ var,
    float* __restrict__ out)
{
    extern __shared__ char sm[];
    const uint32_t sb = smem_u32(sm);
    const int tid = threadIdx.x;
    const int wid = tid >> 5, lid = tid & 31;
    const int blk = blockIdx.x;
    const int b = blk >> 6;
    const int h = blk & 63;

    float4* s_wt = (float4*)(sm + SM_WT);
    ushort4* s_off = (ushort4*)(sm + SM_OFF);
    float* s_sc = (float*)(sm + SM_SC);
    float* s_sh = (float*)(sm + SM_SH);

    const int mbase = (b * 64 + h) * 576;
    for (int i = tid; i < 576; i += 256) {
        s_wt[i] = g_wt[mbase + i];
        s_off[i] = g_offp[mbase + i];
    }
    if (tid < 128) {
        float sc = gamma[tid] * rsqrtf(var[tid] + 1e-5f);
        s_sc[tid] = sc;
        s_sh[tid] = beta[tid] - mean[tid] * sc;
    }
    const float* xb = x + b * CC * HH * WW;
    __syncthreads();

    // warp layout: wM in {0,32}, wN in {0,32,64,96}
    const int wM = (wid & 1) * 32;
    const int wN = (wid >> 1) * 32;
    const int a_row = lid & 15;
    const int a_col = (lid >> 4) * 8;
    const int b_row = (lid & 7) + ((lid >> 4) << 3);
    const int b_col = ((lid >> 3) & 1) * 8;

    float acc[2][4][4];
#pragma unroll
    for (int mt = 0; mt < 2; mt++)
#pragma unroll
        for (int nt = 0; nt < 4; nt++)
#pragma unroll
            for (int i = 0; i < 4; i++) acc[mt][nt][i] = 0.f;

    // prologue: stage chunk 0 into buf 0
    {
        uint32_t bsm = sb + 16384;  // B region of buf0
#pragma unroll
        for (int it = 0; it < 8; it++) {
            int ln = it * 256 + tid;
            cp_async16(bsm + ln * 16, g_wb + ln * 16);
        }
        cp_commit();
        stage_A(sm, xb, s_wt, s_off, 0, tid);
        cp_wait0();
    }
    __syncthreads();

    for (int ch = 0; ch < 18; ch++) {
        const int cur = ch & 1;
        const uint32_t baseA = sb + cur * 49152;
        char* nxt = sm + (cur ^ 1) * 49152;

        // kick off next B copy immediately (lands during MMA + A staging)
        if (ch < 17) {
            uint32_t bsm = sb + (cur ^ 1) * 49152 + 16384;
            const char* gsrc = g_wb + (ch + 1) * 32768;
#pragma unroll
            for (int it = 0; it < 8; it++) {
                int ln = it * 256 + tid;
                cp_async16(bsm + ln * 16, gsrc + ln * 16);
            }
            cp_commit();
        }

#pragma unroll
        for (int ks = 0; ks < 4; ks++) {
            uint32_t ah[2][4], al[2][4];
#pragma unroll
            for (int mt = 0; mt < 2; mt++) {
                uint32_t off = SWZ128((uint32_t)((wM + mt * 16 + a_row) * 128 +
                                                 (ks * 16 + a_col) * 2));
                ldsm_x4(ah[mt], baseA + off);
                ldsm_x4(al[mt], baseA + 8192 + off);
            }
            uint32_t bh[2][4], bl[2][4];
#pragma unroll
            for (int p = 0; p < 2; p++) {
                uint32_t off = SWZ128((uint32_t)((wN + p * 16 + b_row) * 128 +
                                                 (ks * 16 + b_col) * 2));
                ldsm_x4(bh[p], baseA + 16384 + off);
                ldsm_x4(bl[p], baseA + 32768 + off);
            }
#pragma unroll
            for (int mt = 0; mt < 2; mt++)
#pragma unroll
                for (int nt = 0; nt < 4; nt++) {
                    const uint32_t* bhp = &bh[nt >> 1][(nt & 1) * 2];
                    const uint32_t* blp = &bl[nt >> 1][(nt & 1) * 2];
                    mma_bf16(acc[mt][nt], ah[mt], bhp);
                    mma_bf16(acc[mt][nt], ah[mt], blp);
                    mma_bf16(acc[mt][nt], al[mt], bhp);
                }
        }

        if (ch < 17) stage_A(nxt, xb, s_wt, s_off, (ch + 1) * 64, tid);
        cp_wait0();
        __syncthreads();
    }

    // epilogue: BN + SiLU + store
    const int g = lid >> 2, t2 = (lid & 3) * 2;
#pragma unroll
    for (int mt = 0; mt < 2; mt++) {
#pragma unroll
        for (int nt = 0; nt < 4; nt++) {
#pragma unroll
            for (int i = 0; i < 4; i++) {
                int m = wM + mt * 16 + g + ((i >> 1) ? 8 : 0);
                int n = wN + nt * 8 + t2 + (i & 1);
                float v = acc[mt][nt][i] * s_sc[n] + s_sh[n];
                v = v / (1.f + __expf(-v));
                out[((b * OO + n) * HH + h) * WW + m] = v;
            }
        }
    }
}

extern "C" void kernel_launch(void* const* d_in, const int* in_sizes, int n_in,
                              void* d_out, int out_size)
{
    const float* x  = (const float*)d_in[0];
    const float* ow = (const float*)d_in[1];
    const float* ob = (const float*)d_in[2];
    const float* mw = (const float*)d_in[3];
    const float* mb = (const float*)d_in[4];
    const float* wg = (const float*)d_in[5];
    const float* gg = (const float*)d_in[6];
    const float* bt = (const float*)d_in[7];
    const float* mu = (const float*)d_in[8];
    const float* vr = (const float*)d_in[9];
    float* out = (float*)d_out;

    const int SM1 = (1152 * 28 + 4 * 28 * 64) * 4;  // 157,696 B
    cudaFuncSetAttribute(k1_sample_meta,
                         cudaFuncAttributeMaxDynamicSharedMemorySize, SM1);
    cudaFuncSetAttribute(k2_deform_mma,
                         cudaFuncAttributeMaxDynamicSharedMemorySize, SM2_BYTES);

    k0_split_weights<<<288, 256>>>(wg);
    k1_sample_meta<<<BB * HH, 256, SM1>>>(x, ow, ob, mw, mb);
    k2_deform_mma<<<BB * HH, 256, SM2_BYTES>>>(x, gg, bt, mu, vr, out);
}